// round 6
// baseline (speedup 1.0000x reference)
#include <cuda_runtime.h>
#include <cstdint>
#include <math_constants.h>

#define NSEG 128
#define P    512
#define D    64
#define KT   15
#define NC   8
#define NT   1024
#define NW   (NT/32)
#define NCH  4
#define SEG_BYTES   (P * D * 4)            // 131072
#define CHUNK_BYTES (SEG_BYTES / NCH)      // 32768

struct SmemLayout {
    float4             data[P * D / 4];    // 131072 B, offset 0 (16B aligned)
    unsigned long long mbar[NCH];
    float              sdist[P];
    int                slab[P];
    short              sidx[NC][16];
    int                sCnt[NC];
    int                sTaken[NC];
    float              sS[NC];
    float              sM[NC];
    float              sred[NW];
    int                s_last;
};

__device__ float g_partials[NSEG];
__device__ int   g_ticket = 0;   // reset by last block each launch

__device__ __forceinline__ uint32_t smem_u32(const void* p) {
    return (uint32_t)__cvta_generic_to_shared(p);
}

__device__ __forceinline__ void mbar_wait(uint32_t mbar, uint32_t parity) {
    asm volatile(
        "{\n\t.reg .pred P1;\n\t"
        "WAIT_LOOP_%=:\n\t"
        "mbarrier.try_wait.parity.acquire.cta.shared::cta.b64 P1, [%0], %1, 0x989680;\n\t"
        "@P1 bra.uni WAIT_DONE_%=;\n\t"
        "bra.uni WAIT_LOOP_%=;\n\t"
        "WAIT_DONE_%=:\n\t}"
        :: "r"(mbar), "r"(parity) : "memory");
}

__global__ __launch_bounds__(NT, 1)
void lmnn_fused_kernel(const float* __restrict__ center,
                       const float* __restrict__ outputs,
                       const int*   __restrict__ labels,
                       float*       __restrict__ out)
{
    extern __shared__ char smem_raw[];
    SmemLayout* sm = (SmemLayout*)smem_raw;

    const int seg  = blockIdx.x;
    const int t    = threadIdx.x;
    const int w    = t >> 5;
    const int lane = t & 31;

    // ---- init mbarriers, then launch bulk copies (TMA path, no LDGs) ----
    if (t == 0) {
        #pragma unroll
        for (int c = 0; c < NCH; ++c)
            asm volatile("mbarrier.init.shared.b64 [%0], %1;"
                         :: "r"(smem_u32(&sm->mbar[c])), "r"(1u));
        asm volatile("fence.proxy.async.shared::cta;" ::: "memory");
    }
    __syncthreads();

    if (t == 0) {
        const char* gsrc = (const char*)outputs + (size_t)seg * SEG_BYTES;
        #pragma unroll
        for (int c = 0; c < NCH; ++c) {
            const uint32_t mb = smem_u32(&sm->mbar[c]);
            asm volatile("mbarrier.arrive.expect_tx.shared.b64 _, [%0], %1;"
                         :: "r"(mb), "r"((uint32_t)CHUNK_BYTES) : "memory");
            asm volatile(
                "cp.async.bulk.shared::cluster.global.mbarrier::complete_tx::bytes "
                "[%0], [%1], %2, [%3];"
                :: "r"(smem_u32((char*)sm->data + c * CHUNK_BYTES)),
                   "l"(gsrc + c * CHUNK_BYTES),
                   "r"((uint32_t)CHUNK_BYTES), "r"(mb) : "memory");
        }
    }

    // center float4 for this thread's d-offset (constant across chunks)
    const float4 c4 = __ldg(&((const float4*)(center + seg * D))[t & 15]);

    // ---- class scan on labels (warps 0..7), overlapped with TMA flight ----
    // top_k over -dd has all finite entries equal (dist broadcast along k),
    // so jax tie-breaking selects the FIRST KT same-class indices.
    if (w < NC) {
        int lab[16];
        #pragma unroll
        for (int u = 0; u < 16; ++u)
            lab[u] = __ldg(&labels[seg * P + u * 32 + lane]);
        if (w == 0) {
            #pragma unroll
            for (int u = 0; u < 16; ++u)
                sm->slab[u * 32 + lane] = lab[u];
        }
        int cnt = 0, taken = 0;
        #pragma unroll
        for (int u = 0; u < 16; ++u) {
            const bool m = (lab[u] == w);
            const unsigned mask = __ballot_sync(0xffffffffu, m);
            const int pc = __popc(mask);
            const int need = KT - taken;
            if (need > 0) {
                const int rank = __popc(mask & ((1u << lane) - 1u));
                if (m && rank < need)
                    sm->sidx[w][taken + rank] = (short)(u * 32 + lane);
                taken += (pc < need) ? pc : need;
            }
            cnt += pc;
        }
        if (lane == 0) { sm->sCnt[w] = cnt; sm->sTaken[w] = taken; }
    }

    // ---- distance compute, pipelined per 32KB chunk ----
    // chunk c holds float4 indices [c*2048, (c+1)*2048) = g = t + 1024*s,
    // s in {2c, 2c+1}. 16 lanes = one point.
    #pragma unroll
    for (int c = 0; c < NCH; ++c) {
        mbar_wait(smem_u32(&sm->mbar[c]), 0u);
        #pragma unroll
        for (int s2 = 0; s2 < 2; ++s2) {
            const int g = t + NT * (2 * c + s2);
            const float4 v = sm->data[g];
            const float dx = v.x - c4.x;
            const float dy = v.y - c4.y;
            const float dz = v.z - c4.z;
            const float dw = v.w - c4.w;
            float part = dx * dx + dy * dy + dz * dz + dw * dw;
            part += __shfl_down_sync(0xffffffffu, part, 8);
            part += __shfl_down_sync(0xffffffffu, part, 4);
            part += __shfl_down_sync(0xffffffffu, part, 2);
            part += __shfl_down_sync(0xffffffffu, part, 1);
            if ((t & 15) == 0) sm->sdist[g >> 4] = part;
        }
    }
    __syncthreads();

    // ---- gather first-KT distances per class (warps 0..7) ----
    if (w < NC) {
        const int cnt   = sm->sCnt[w];
        const int taken = sm->sTaken[w];
        float d = (lane < KT)
                    ? ((lane < taken) ? sm->sdist[sm->sidx[w][lane]] : CUDART_INF_F)
                    : 0.0f;
        float S  = (lane < KT) ? d : 0.0f;
        float Mx = (lane < KT) ? d : -CUDART_INF_F;
        #pragma unroll
        for (int off = 16; off > 0; off >>= 1) {
            S += __shfl_xor_sync(0xffffffffu, S, off);
            Mx = fmaxf(Mx, __shfl_xor_sync(0xffffffffu, Mx, off));
        }
        if (lane == 0) {
            sm->sS[w] = (cnt > 0) ? S : 0.0f;
            sm->sM[w] = (cnt > 0) ? Mx : -CUDART_INF_F;
        }
    }
    __syncthreads();

    // ---- margin_seg = 1 + max over present classes ----
    float ms = -CUDART_INF_F;
    #pragma unroll
    for (int c = 0; c < NC; ++c)
        ms = fmaxf(ms, sm->sM[c]);
    ms += 1.0f;

    // ---- push term per point (first 512 threads) ----
    float term = 0.0f;
    if (t < P) {
        const int   cj = sm->slab[t];
        const float dv = sm->sdist[t];
        if (dv < ms)
            term = (float)(P - sm->sCnt[cj]) * fmaxf(1.0f + sm->sM[cj] - dv, 0.0f);
    }
    #pragma unroll
    for (int off = 16; off > 0; off >>= 1)
        term += __shfl_xor_sync(0xffffffffu, term, off);
    if (lane == 0) sm->sred[w] = term;
    __syncthreads();

    // ---- per-segment partial + last-block finish ----
    if (t == 0) {
        float push = 0.0f;
        #pragma unroll
        for (int k = 0; k < NW; ++k) push += sm->sred[k];
        float pull = 0.0f;
        #pragma unroll
        for (int c = 0; c < NC; ++c)
            pull += (float)sm->sCnt[c] * sm->sS[c];
        g_partials[seg] = pull + push;
        __threadfence();
        const int prev = atomicAdd(&g_ticket, 1);
        sm->s_last = (prev == NSEG - 1) ? 1 : 0;
    }
    __syncthreads();

    if (sm->s_last && w == 0) {
        __threadfence();
        const float a  = g_partials[lane];
        const float b  = g_partials[lane + 32];
        const float c2 = g_partials[lane + 64];
        const float d2 = g_partials[lane + 96];
        float vsum = (a + b) + (c2 + d2);
        #pragma unroll
        for (int off = 16; off > 0; off >>= 1)
            vsum += __shfl_xor_sync(0xffffffffu, vsum, off);
        if (lane == 0) {
            out[0] = vsum * (1.0f / (float)(NSEG * P));
            g_ticket = 0;   // reset for next graph replay
        }
    }
}

extern "C" void kernel_launch(void* const* d_in, const int* in_sizes, int n_in,
                              void* d_out, int out_size)
{
    const float* center  = (const float*)d_in[0];  // (128, 64)    f32
    const float* outputs = (const float*)d_in[1];  // (128,512,64) f32
    const int*   labels  = (const int*)d_in[2];    // (128, 512)   i32

    cudaFuncSetAttribute(lmnn_fused_kernel,
                         cudaFuncAttributeMaxDynamicSharedMemorySize,
                         (int)sizeof(SmemLayout));
    lmnn_fused_kernel<<<NSEG, NT, sizeof(SmemLayout)>>>(
        center, outputs, labels, (float*)d_out);
}